// round 9
// baseline (speedup 1.0000x reference)
#include <cuda_runtime.h>
#include <cuda_bf16.h>
#include <stdint.h>

#define NC 256      // clusters
#define NP 128      // points per cluster
#define VS3 (32*32*32)

// scratch (allocation-free rule: __device__ globals)
__device__ float g_c1 [NC * 16 * 4096];      // 64 MB (conv1 output, linear, no bias/relu)
__device__ float g_W2t[4 * 3456];            // W2 permuted: [icg][(icl*27+k)*32 + oc]
__device__ float g_W3t[8 * 6912];            // W3 permuted: [icg][(icl*27+k)*64 + ocg*8+o]

// ---------------------------------------------------------------- K1: wprep + voxelize + conv1
#define K1_FLOATS (32*32*33 + 432)
__global__ void __launch_bounds__(512) voxconv1_kernel(
    const float* __restrict__ data, const int* __restrict__ clusts,
    const int* __restrict__ mask, const float* __restrict__ W1,
    const float* __restrict__ W2, const float* __restrict__ W3)
{
    extern __shared__ float vsh[];           // [32*32][33] then w1s
    float* w1s = vsh + 32*32*33;
    const int c = blockIdx.x;
    const int tid = threadIdx.x;

    // --- merged weight permute (spread across blocks; edge runs after this kernel) ---
    {
        int gid = c*512 + tid;
        if (gid < 4*3456) {
            int icg = gid / 3456, r = gid % 3456;
            int row = r >> 5, oc = r & 31;
            int icl = row / 27, k = row % 27;
            g_W2t[gid] = W2[oc*432 + (icg*4 + icl)*27 + k];
        }
        if (gid < 8*6912) {
            int icg = gid / 6912, r = gid % 6912;
            int row = r >> 6, cc = r & 63;
            int ocg = cc >> 3, o = cc & 7;
            int icl = row / 27, k = row % 27;
            g_W3t[gid] = W3[(o*8 + ocg)*864 + (icg*4 + icl)*27 + k];
        }
    }

    float4* v4 = reinterpret_cast<float4*>(vsh);
    #pragma unroll
    for (int i = tid; i < (32*32*33)/4; i += 512) v4[i] = make_float4(0.f,0.f,0.f,0.f);
    if (tid < 432) w1s[tid] = W1[tid];

    const int p   = tid & 127;
    const int sub = tid >> 7;                // 0..3 quadrant of (i,j) splat space
    const int idx = clusts[c*NP + p];
    const bool m = mask[c*NP + p] != 0;
    const float px = data[idx*5+0];
    const float py = data[idx*5+1];
    const float pz = data[idx*5+2];
    const float val = data[idx*5+4];

    const float BIG = 1e9f;
    float mn[3], mx[3];
    mn[0] = m ? px :  BIG; mn[1] = m ? py :  BIG; mn[2] = m ? pz :  BIG;
    mx[0] = m ? px : -BIG; mx[1] = m ? py : -BIG; mx[2] = m ? pz : -BIG;
    #pragma unroll
    for (int off = 16; off; off >>= 1) {
        #pragma unroll
        for (int a = 0; a < 3; a++) {
            mn[a] = fminf(mn[a], __shfl_xor_sync(0xffffffffu, mn[a], off));
            mx[a] = fmaxf(mx[a], __shfl_xor_sync(0xffffffffu, mx[a], off));
        }
    }
    __shared__ float wmn[16][3], wmx[16][3];
    __shared__ float smins[3], srng[3], sgs;
    if ((tid & 31) == 0) {
        #pragma unroll
        for (int a = 0; a < 3; a++) { wmn[tid>>5][a] = mn[a]; wmx[tid>>5][a] = mx[a]; }
    }
    __syncthreads();
    if (tid == 0) {
        float rmax = -BIG;
        #pragma unroll
        for (int a = 0; a < 3; a++) {
            float lo = BIG, hi = -BIG;
            #pragma unroll
            for (int w = 0; w < 16; w++) { lo = fminf(lo, wmn[w][a]); hi = fmaxf(hi, wmx[w][a]); }
            smins[a] = lo;
            srng[a]  = hi - lo;
            rmax = fmaxf(rmax, hi - lo);
        }
        sgs = 1.0f / (rmax + 1.0f);
    }
    __syncthreads();

    if (m) {
        const float gs = sgs;
        const float ns = 1.0f / 32.0f;
        float v[3];
        v[0] = (px - smins[0] - srng[0]*0.5f - 0.5f) * gs + 0.5f;
        v[1] = (py - smins[1] - srng[1]*0.5f - 0.5f) * gs + 0.5f;
        v[2] = (pz - smins[2] - srng[2]*0.5f - 0.5f) * gs + 0.5f;
        int i0[3], i1[3];
        #pragma unroll
        for (int a = 0; a < 3; a++) {
            i0[a] = max(0,  (int)floorf(v[a] * 32.0f));
            i1[a] = min(31, (int)floorf((v[a] + gs) * 32.0f));
        }
        for (int i = i0[0] + (sub & 1); i <= i1[0]; i += 2) {
            float lo = (float)i * ns;
            float ox = fmaxf(fminf(v[0]+gs, lo+ns) - fmaxf(v[0], lo), 0.f) / gs;
            for (int j = i0[1] + (sub >> 1); j <= i1[1]; j += 2) {
                lo = (float)j * ns;
                float oy  = fmaxf(fminf(v[1]+gs, lo+ns) - fmaxf(v[1], lo), 0.f) / gs;
                float pre = val * ox * oy;
                for (int k = i0[2]; k <= i1[2]; k++) {
                    lo = (float)k * ns;
                    float oz = fmaxf(fminf(v[2]+gs, lo+ns) - fmaxf(v[2], lo), 0.f) / gs;
                    atomicAdd(&vsh[(i*32 + j)*33 + k], pre * oz);
                }
            }
        }
    }
    __syncthreads();

    // ---- conv1 phase (reads vsh directly) ----
    const int od  = tid >> 5;
    const int oh  = (tid >> 1) & 15;
    const int owh = tid & 1;
    float* outp = g_c1 + (size_t)c * 16 * 4096;

    for (int ocg = 0; ocg < 4; ocg++) {
        float acc[4][8];
        #pragma unroll
        for (int o = 0; o < 4; o++)
            #pragma unroll
            for (int i = 0; i < 8; i++) acc[o][i] = 0.f;

        #pragma unroll
        for (int kd = 0; kd < 3; kd++) {
            int d = 2*od + kd;
            #pragma unroll
            for (int kh = 0; kh < 3; kh++) {
                int h = 2*oh + kh;
                bool valid = (d < 32) && (h < 32);
                float xv[17];
                #pragma unroll
                for (int t = 0; t < 17; t++) {
                    int wabs = owh*16 + t;
                    xv[t] = (valid && wabs < 32) ? vsh[(d*32 + h)*33 + wabs] : 0.f;
                }
                #pragma unroll
                for (int o = 0; o < 4; o++) {
                    int oc = ocg*4 + o;
                    #pragma unroll
                    for (int kw = 0; kw < 3; kw++) {
                        float wv = w1s[oc*27 + kd*9 + kh*3 + kw];
                        #pragma unroll
                        for (int i = 0; i < 8; i++)
                            acc[o][i] = fmaf(xv[2*i + kw], wv, acc[o][i]);
                    }
                }
            }
        }
        #pragma unroll
        for (int o = 0; o < 4; o++)
            #pragma unroll
            for (int i = 0; i < 8; i++)
                outp[(ocg*4 + o)*4096 + (od*16 + oh)*16 + owh*8 + i] = acc[o][i];
    }
}

// ---------------------------------------------------------------- K2: per-edge fused (2 CTAs/SM)
// smem (floats), total 27072 = 108,288 B:
//   ybuf: [0, 16416)          32 oc * 513 (odd stride: conflict-free oc-major stores)
//   xbuf: [16416, 23616)      4 ic * 90 rows * 20  (quarter of conv2 input; zero-padded)
//   wbuf2:[23616, 27072)      3456
//   wbuf3:[16416, 23328)      overlay on xbuf (conv3 phase)
//   zbuf: [0, 4160)           64 oc * 65, overlay on ybuf (post-conv3)
//   pooled:[4160, 4224)
#define EYB 0
#define EXB 16416
#define EWB2 23616
#define E_FLOATS (23616 + 3456)
#define E_SMEM (E_FLOATS * 4)

#define EFMA(OW, T, W) acc[OW] = fmaf(T, W, acc[OW]);
#define EFMA_KW(W, T0,T1,T2,T3,T4,T5,T6,T7) \
    EFMA(0,T0,W) EFMA(1,T1,W) EFMA(2,T2,W) EFMA(3,T3,W) \
    EFMA(4,T4,W) EFMA(5,T5,W) EFMA(6,T6,W) EFMA(7,T7,W)

__global__ void __launch_bounds__(512, 2) edge_kernel(
    const int* __restrict__ eidx, int E, int cmax,
    const float* __restrict__ b1,
    const float* __restrict__ b2,
    const float* __restrict__ b3, const float* __restrict__ Wfc,
    const float* __restrict__ bfc, float* __restrict__ out)
{
    extern __shared__ float sh[];
    float* ybuf  = sh + EYB;
    float* xbuf  = sh + EXB;
    float* wbuf2 = sh + EWB2;
    float* wbuf3 = sh + EXB;     // overlay
    float* zbuf  = sh + EYB;     // overlay
    float* pooled= sh + 4160;
    __shared__ float sb1[16], sb2[32];

    const int e = blockIdx.x;
    const int tid = threadIdx.x;
    const int ei = min(max(eidx[e], 0), cmax);
    const int ej = min(max(eidx[E + e], 0), cmax);
    const float* ci = g_c1 + (size_t)ei * 16 * 4096;
    const float* cj = g_c1 + (size_t)ej * 16 * 4096;

    // init: zero xbuf (establishes zero rows h=16 and pad cols 16..19), stage biases
    for (int i = tid; i < 7200; i += 512) xbuf[i] = 0.f;
    if (tid < 16) sb1[tid] = b1[tid];
    else if (tid < 48) sb2[tid-16] = b2[tid-16];
    __syncthreads();

    // conv2: thread = (odp = (tid>>5)>>3, oh = (tid>>5)&7, ocg = tid&31); 1 oc x 8 ow
    const int sp  = tid >> 5;
    const int odp = sp >> 3;     // 0..1 (within quarter)
    const int oh2 = sp & 7;
    const int ocg = tid & 31;

    float acc[8] = {0,0,0,0,0,0,0,0};

    for (int q = 0; q < 4; q++) {
        for (int icg = 0; icg < 4; icg++) {
            // stage x quarter: 4 ic x 5 d-slabs x 16 h x 16 w  (float4 granularity)
            for (int fi = tid; fi < 1280; fi += 512) {
                int icl = fi / 320;
                int r   = fi - icl*320;
                int dl  = r >> 6;
                int r2  = r & 63;
                int h   = r2 >> 2;
                int w4  = (r2 & 3) * 4;
                int d   = 4*q + dl;
                float4 v = make_float4(0.f,0.f,0.f,0.f);
                if (d < 16) {
                    int off = (icg*4 + icl)*4096 + d*256 + h*16 + w4;
                    float4 a = *reinterpret_cast<const float4*>(ci + off);
                    float4 b = *reinterpret_cast<const float4*>(cj + off);
                    float bb = sb1[icg*4 + icl];
                    v.x = fmaxf(a.x + b.x + bb, 0.f);
                    v.y = fmaxf(a.y + b.y + bb, 0.f);
                    v.z = fmaxf(a.z + b.z + bb, 0.f);
                    v.w = fmaxf(a.w + b.w + bb, 0.f);
                }
                *reinterpret_cast<float4*>(&xbuf[(icl*90 + dl*18 + h)*20 + w4]) = v;
            }
            // stage W2 chunk: coalesced float4 copy
            {
                const float4* src = reinterpret_cast<const float4*>(g_W2t + icg*3456);
                float4* dst = reinterpret_cast<float4*>(wbuf2);
                for (int i = tid; i < 864; i += 512) dst[i] = src[i];
            }
            __syncthreads();

            #pragma unroll
            for (int icl = 0; icl < 4; icl++) {
                #pragma unroll
                for (int kd = 0; kd < 3; kd++) {
                    int dl = 2*odp + kd;
                    #pragma unroll
                    for (int kh = 0; kh < 3; kh++) {
                        int h = 2*oh2 + kh;     // 0..16 (16 -> zero row)
                        const float* rp = &xbuf[(icl*90 + dl*18 + h)*20];
                        const float4 A0 = *reinterpret_cast<const float4*>(rp);
                        const float4 A1 = *reinterpret_cast<const float4*>(rp + 4);
                        const float4 A2 = *reinterpret_cast<const float4*>(rp + 8);
                        const float4 A3 = *reinterpret_cast<const float4*>(rp + 12);
                        const float X16 = rp[16];
                        const float* wk = &wbuf2[(icl*27 + kd*9 + kh*3)*32 + ocg];
                        const float w0 = wk[0], w1 = wk[32], w2 = wk[64];
                        EFMA_KW(w0, A0.x,A0.z,A1.x,A1.z,A2.x,A2.z,A3.x,A3.z)
                        EFMA_KW(w1, A0.y,A0.w,A1.y,A1.w,A2.y,A2.w,A3.y,A3.w)
                        EFMA_KW(w2, A0.z,A1.x,A1.z,A2.x,A2.z,A3.x,A3.z,X16)
                    }
                }
            }
            __syncthreads();
        }
        // y quarter = relu(acc + b2) -> ybuf (odd stride 513: conflict-free)
        {
            float bb = sb2[ocg];
            int base = ocg*513 + (2*q + odp)*64 + oh2*8;
            #pragma unroll
            for (int ow = 0; ow < 8; ow++) {
                ybuf[base + ow] = fmaxf(acc[ow] + bb, 0.f);
                acc[ow] = 0.f;
            }
        }
    }
    __syncthreads();

    // conv3: thread = (sp3 = tid>>3, ocg3 = tid&7), 8 oc each
    const int sp3 = tid >> 3;
    const int ocg3 = tid & 7;
    const int od3 = sp3 >> 4, oh3 = (sp3 >> 2) & 3, ow3 = sp3 & 3;
    float acc3[8] = {0,0,0,0,0,0,0,0};

    for (int icg = 0; icg < 8; icg++) {
        {
            const float4* src = reinterpret_cast<const float4*>(g_W3t + icg*6912);
            float4* dst = reinterpret_cast<float4*>(wbuf3);
            for (int i = tid; i < 1728; i += 512) dst[i] = src[i];
        }
        __syncthreads();
        #pragma unroll
        for (int icl = 0; icl < 4; icl++) {
            const float* yb = &ybuf[(icg*4 + icl)*513];
            float yv[27];
            #pragma unroll
            for (int kd = 0; kd < 3; kd++) {
                int d = 2*od3 + kd;
                #pragma unroll
                for (int kh = 0; kh < 3; kh++) {
                    int h = 2*oh3 + kh;
                    #pragma unroll
                    for (int kw = 0; kw < 3; kw++) {
                        int w = 2*ow3 + kw;
                        yv[kd*9 + kh*3 + kw] =
                            (d < 8 && h < 8 && w < 8) ? yb[d*64 + h*8 + w] : 0.f;
                    }
                }
            }
            #pragma unroll
            for (int k = 0; k < 27; k++) {
                const float* wrow = &wbuf3[(icl*27 + k)*64 + ocg3*8];
                float4 wa = *reinterpret_cast<const float4*>(wrow);
                float4 wb = *reinterpret_cast<const float4*>(wrow + 4);
                float yk = yv[k];
                acc3[0] = fmaf(yk, wa.x, acc3[0]);
                acc3[1] = fmaf(yk, wa.y, acc3[1]);
                acc3[2] = fmaf(yk, wa.z, acc3[2]);
                acc3[3] = fmaf(yk, wa.w, acc3[3]);
                acc3[4] = fmaf(yk, wb.x, acc3[4]);
                acc3[5] = fmaf(yk, wb.y, acc3[5]);
                acc3[6] = fmaf(yk, wb.z, acc3[6]);
                acc3[7] = fmaf(yk, wb.w, acc3[7]);
            }
        }
        __syncthreads();
    }

    // z = relu(acc3 + b3) -> zbuf (stride 65; ybuf fully consumed)
    #pragma unroll
    for (int o = 0; o < 8; o++) {
        int oc = o*8 + ocg3;
        zbuf[oc*65 + sp3] = fmaxf(acc3[o] + b3[oc], 0.f);
    }
    __syncthreads();

    if (tid < 64) {
        float s = 0.f;
        #pragma unroll 8
        for (int qq = 0; qq < 64; qq++) s += zbuf[tid*65 + qq];
        pooled[tid] = s * (1.f/64.f);
    }
    __syncthreads();
    if (tid < 64) {
        float a = bfc[tid];
        #pragma unroll 8
        for (int ic = 0; ic < 64; ic++)
            a = fmaf(pooled[ic], Wfc[ic*64 + tid], a);
        out[e*64 + tid] = a;
    }
}

// ---------------------------------------------------------------- launch
extern "C" void kernel_launch(void* const* d_in, const int* in_sizes, int n_in,
                              void* d_out, int out_size)
{
    const float* data   = (const float*)d_in[0];
    const int*   clusts = (const int*)d_in[1];
    const int*   cmask  = (const int*)d_in[2];
    const int*   eidx   = (const int*)d_in[3];
    const float* W1  = (const float*)d_in[4];
    const float* b1  = (const float*)d_in[5];
    const float* W2  = (const float*)d_in[6];
    const float* b2  = (const float*)d_in[7];
    const float* W3  = (const float*)d_in[8];
    const float* b3  = (const float*)d_in[9];
    const float* Wfc = (const float*)d_in[10];
    const float* bfc = (const float*)d_in[11];
    float* out = (float*)d_out;

    const int C = in_sizes[1] / NP;       // 256
    const int E = in_sizes[3] / 2;        // 1024

    cudaFuncSetAttribute(voxconv1_kernel, cudaFuncAttributeMaxDynamicSharedMemorySize, K1_FLOATS*4);
    cudaFuncSetAttribute(edge_kernel,     cudaFuncAttributeMaxDynamicSharedMemorySize, E_SMEM);

    voxconv1_kernel<<<C, 512, K1_FLOATS*4>>>(data, clusts, cmask, W1, W2, W3);
    edge_kernel    <<<E, 512, E_SMEM>>>(eidx, E, C - 1, b1, b2, b3, Wfc, bfc, out);
}

// round 10
// speedup vs baseline: 1.0301x; 1.0301x over previous
#include <cuda_runtime.h>
#include <cuda_bf16.h>
#include <stdint.h>

#define NC 256      // clusters
#define NP 128      // points per cluster

// scratch (allocation-free rule: __device__ globals)
__device__ float g_c1 [NC * 16 * 4096];      // 64 MB (conv1 output, linear, no bias/relu)
__device__ float g_y  [1024 * 16384];        // 64 MB (per-edge conv2 output, L2-resident)
__device__ float g_W2t[4 * 3456];            // W2 permuted: [icg][(icl*27+k)*32 + oc]
__device__ float g_W3t[8 * 6912];            // W3 permuted: [icg][(icl*27+k)*64 + ocg*8+o]

// ---------------------------------------------------------------- K1: wprep + voxelize + conv1
#define K1_FLOATS (32*32*33 + 432)
__global__ void __launch_bounds__(512) voxconv1_kernel(
    const float* __restrict__ data, const int* __restrict__ clusts,
    const int* __restrict__ mask, const float* __restrict__ W1,
    const float* __restrict__ W2, const float* __restrict__ W3)
{
    extern __shared__ float vsh[];           // [32*32][33] then w1s
    float* w1s = vsh + 32*32*33;
    const int c = blockIdx.x;
    const int tid = threadIdx.x;

    // --- merged weight permute (spread across blocks) ---
    {
        int gid = c*512 + tid;
        if (gid < 4*3456) {
            int icg = gid / 3456, r = gid % 3456;
            int row = r >> 5, oc = r & 31;
            int icl = row / 27, k = row % 27;
            g_W2t[gid] = W2[oc*432 + (icg*4 + icl)*27 + k];
        }
        if (gid < 8*6912) {
            int icg = gid / 6912, r = gid % 6912;
            int row = r >> 6, cc = r & 63;
            int ocg = cc >> 3, o = cc & 7;
            int icl = row / 27, k = row % 27;
            g_W3t[gid] = W3[(o*8 + ocg)*864 + (icg*4 + icl)*27 + k];
        }
    }

    float4* v4 = reinterpret_cast<float4*>(vsh);
    #pragma unroll
    for (int i = tid; i < (32*32*33)/4; i += 512) v4[i] = make_float4(0.f,0.f,0.f,0.f);
    if (tid < 432) w1s[tid] = W1[tid];

    const int p   = tid & 127;
    const int sub = tid >> 7;                // 0..3 quadrant of (i,j) splat space
    const int idx = clusts[c*NP + p];
    const bool m = mask[c*NP + p] != 0;
    const float px = data[idx*5+0];
    const float py = data[idx*5+1];
    const float pz = data[idx*5+2];
    const float val = data[idx*5+4];

    const float BIG = 1e9f;
    float mn[3], mx[3];
    mn[0] = m ? px :  BIG; mn[1] = m ? py :  BIG; mn[2] = m ? pz :  BIG;
    mx[0] = m ? px : -BIG; mx[1] = m ? py : -BIG; mx[2] = m ? pz : -BIG;
    #pragma unroll
    for (int off = 16; off; off >>= 1) {
        #pragma unroll
        for (int a = 0; a < 3; a++) {
            mn[a] = fminf(mn[a], __shfl_xor_sync(0xffffffffu, mn[a], off));
            mx[a] = fmaxf(mx[a], __shfl_xor_sync(0xffffffffu, mx[a], off));
        }
    }
    __shared__ float wmn[16][3], wmx[16][3];
    __shared__ float smins[3], srng[3], sgs;
    if ((tid & 31) == 0) {
        #pragma unroll
        for (int a = 0; a < 3; a++) { wmn[tid>>5][a] = mn[a]; wmx[tid>>5][a] = mx[a]; }
    }
    __syncthreads();
    if (tid == 0) {
        float rmax = -BIG;
        #pragma unroll
        for (int a = 0; a < 3; a++) {
            float lo = BIG, hi = -BIG;
            #pragma unroll
            for (int w = 0; w < 16; w++) { lo = fminf(lo, wmn[w][a]); hi = fmaxf(hi, wmx[w][a]); }
            smins[a] = lo;
            srng[a]  = hi - lo;
            rmax = fmaxf(rmax, hi - lo);
        }
        sgs = 1.0f / (rmax + 1.0f);
    }
    __syncthreads();

    if (m) {
        const float gs = sgs;
        const float ns = 1.0f / 32.0f;
        float v[3];
        v[0] = (px - smins[0] - srng[0]*0.5f - 0.5f) * gs + 0.5f;
        v[1] = (py - smins[1] - srng[1]*0.5f - 0.5f) * gs + 0.5f;
        v[2] = (pz - smins[2] - srng[2]*0.5f - 0.5f) * gs + 0.5f;
        int i0[3], i1[3];
        #pragma unroll
        for (int a = 0; a < 3; a++) {
            i0[a] = max(0,  (int)floorf(v[a] * 32.0f));
            i1[a] = min(31, (int)floorf((v[a] + gs) * 32.0f));
        }
        for (int i = i0[0] + (sub & 1); i <= i1[0]; i += 2) {
            float lo = (float)i * ns;
            float ox = fmaxf(fminf(v[0]+gs, lo+ns) - fmaxf(v[0], lo), 0.f) / gs;
            for (int j = i0[1] + (sub >> 1); j <= i1[1]; j += 2) {
                lo = (float)j * ns;
                float oy  = fmaxf(fminf(v[1]+gs, lo+ns) - fmaxf(v[1], lo), 0.f) / gs;
                float pre = val * ox * oy;
                for (int k = i0[2]; k <= i1[2]; k++) {
                    lo = (float)k * ns;
                    float oz = fmaxf(fminf(v[2]+gs, lo+ns) - fmaxf(v[2], lo), 0.f) / gs;
                    atomicAdd(&vsh[(i*32 + j)*33 + k], pre * oz);
                }
            }
        }
    }
    __syncthreads();

    // ---- conv1 phase ----
    const int od  = tid >> 5;
    const int oh  = (tid >> 1) & 15;
    const int owh = tid & 1;
    float* outp = g_c1 + (size_t)c * 16 * 4096;

    for (int ocg = 0; ocg < 4; ocg++) {
        float acc[4][8];
        #pragma unroll
        for (int o = 0; o < 4; o++)
            #pragma unroll
            for (int i = 0; i < 8; i++) acc[o][i] = 0.f;

        #pragma unroll
        for (int kd = 0; kd < 3; kd++) {
            int d = 2*od + kd;
            #pragma unroll
            for (int kh = 0; kh < 3; kh++) {
                int h = 2*oh + kh;
                bool valid = (d < 32) && (h < 32);
                float xv[17];
                #pragma unroll
                for (int t = 0; t < 17; t++) {
                    int wabs = owh*16 + t;
                    xv[t] = (valid && wabs < 32) ? vsh[(d*32 + h)*33 + wabs] : 0.f;
                }
                #pragma unroll
                for (int o = 0; o < 4; o++) {
                    int oc = ocg*4 + o;
                    #pragma unroll
                    for (int kw = 0; kw < 3; kw++) {
                        float wv = w1s[oc*27 + kd*9 + kh*3 + kw];
                        #pragma unroll
                        for (int i = 0; i < 8; i++)
                            acc[o][i] = fmaf(xv[2*i + kw], wv, acc[o][i]);
                    }
                }
            }
        }
        #pragma unroll
        for (int o = 0; o < 4; o++)
            #pragma unroll
            for (int i = 0; i < 8; i++)
                outp[(ocg*4 + o)*4096 + (od*16 + oh)*16 + owh*8 + i] = acc[o][i];
    }
}

// ---------------------------------------------------------------- K2: per-edge fused (2 CTAs/SM)
// smem (floats), total 16416 = 65.7 KB:
//  phase A (conv2): xbuf [0,12960) = 4ic * 9 slabs * 18 rows * 20 cols; wbuf2 [12960,16416)
//  phase B (conv3): ystage [0,2080) = 4ic*520; wbuf3 [2080,8992); zbuf [8992,13152) = 64*65;
//                   pooled [13152,13216)
#define EXB   0
#define EWB2  12960
#define EYS   0
#define EWB3  2080
#define EZB   8992
#define EPOOL 13152
#define E_FLOATS 16416
#define E_SMEM (E_FLOATS * 4)

// per-tap: 2 oc (a=ocp, b=ocp+16) x 8 ow
#define EF2(OW, T, WA, WB) \
    acc[0][OW] = fmaf(T, WA, acc[0][OW]); \
    acc[1][OW] = fmaf(T, WB, acc[1][OW]);
#define EF2_KW(WA, WB, T0,T1,T2,T3,T4,T5,T6,T7) \
    EF2(0,T0,WA,WB) EF2(1,T1,WA,WB) EF2(2,T2,WA,WB) EF2(3,T3,WA,WB) \
    EF2(4,T4,WA,WB) EF2(5,T5,WA,WB) EF2(6,T6,WA,WB) EF2(7,T7,WA,WB)

__global__ void __launch_bounds__(512, 2) edge_kernel(
    const int* __restrict__ eidx, int E, int cmax,
    const float* __restrict__ b1,
    const float* __restrict__ b2,
    const float* __restrict__ b3, const float* __restrict__ Wfc,
    const float* __restrict__ bfc, float* __restrict__ out)
{
    extern __shared__ float sh[];
    float* xbuf  = sh + EXB;
    float* wbuf2 = sh + EWB2;
    float* ystage= sh + EYS;
    float* wbuf3 = sh + EWB3;
    float* zbuf  = sh + EZB;
    float* pooled= sh + EPOOL;
    __shared__ float sb1[16], sb2[32];

    const int e = blockIdx.x;
    const int tid = threadIdx.x;
    const int ei = min(max(eidx[e], 0), cmax);
    const int ej = min(max(eidx[E + e], 0), cmax);
    const float* ci = g_c1 + (size_t)ei * 16 * 4096;
    const float* cj = g_c1 + (size_t)ej * 16 * 4096;
    float* ye = g_y + (size_t)e * 16384;

    if (tid < 16) sb1[tid] = b1[tid];
    else if (tid < 48) sb2[tid-16] = b2[tid-16];
    __syncthreads();

    // conv2 mapping: warp w=tid>>5; lane: s=lane>>4 (row in pair), ocp=lane&15
    // spatial row r = 2w+s in half-volume: od_l = r>>3 (0..3), oh = r&7
    const int lane = tid & 31;
    const int s    = lane >> 4;
    const int ocp  = lane & 15;
    const int r    = 2*(tid >> 5) + s;
    const int od_l = r >> 3;
    const int oh2  = r & 7;

    float acc[2][8];
    #pragma unroll
    for (int o = 0; o < 2; o++)
        #pragma unroll
        for (int w = 0; w < 8; w++) acc[o][w] = 0.f;

    for (int q = 0; q < 2; q++) {
        for (int icg = 0; icg < 4; icg++) {
            // stage x half: 4ic x 9 d-slabs x 18 rows x 5 float4 (zeros beyond data)
            for (int fi = tid; fi < 3240; fi += 512) {
                int icl = fi / 810;
                int rr  = fi - icl*810;
                int dl  = rr / 90;
                int r2  = rr - dl*90;
                int rh  = r2 / 5;
                int w4  = (r2 - rh*5) * 4;
                int d   = 8*q + dl;
                float4 v = make_float4(0.f,0.f,0.f,0.f);
                if (d < 16 && rh < 16 && w4 < 16) {
                    int off = (icg*4 + icl)*4096 + d*256 + rh*16 + w4;
                    float4 a = *reinterpret_cast<const float4*>(ci + off);
                    float4 b = *reinterpret_cast<const float4*>(cj + off);
                    float bb = sb1[icg*4 + icl];
                    v.x = fmaxf(a.x + b.x + bb, 0.f);
                    v.y = fmaxf(a.y + b.y + bb, 0.f);
                    v.z = fmaxf(a.z + b.z + bb, 0.f);
                    v.w = fmaxf(a.w + b.w + bb, 0.f);
                }
                *reinterpret_cast<float4*>(&xbuf[((icl*9 + dl)*18 + rh)*20 + w4]) = v;
            }
            // stage W2 chunk (coalesced float4)
            {
                const float4* src = reinterpret_cast<const float4*>(g_W2t + icg*3456);
                float4* dst = reinterpret_cast<float4*>(wbuf2);
                for (int i = tid; i < 864; i += 512) dst[i] = src[i];
            }
            __syncthreads();

            #pragma unroll
            for (int icl = 0; icl < 4; icl++) {
                #pragma unroll
                for (int kd = 0; kd < 3; kd++) {
                    int dl = 2*od_l + kd;           // 0..8
                    #pragma unroll
                    for (int kh = 0; kh < 3; kh++) {
                        int h = 2*oh2 + kh;         // 0..16 (16 -> zero row)
                        const float* rp = &xbuf[((icl*9 + dl)*18 + h)*20];
                        const float4 A0 = *reinterpret_cast<const float4*>(rp);
                        const float4 A1 = *reinterpret_cast<const float4*>(rp + 4);
                        const float4 A2 = *reinterpret_cast<const float4*>(rp + 8);
                        const float4 A3 = *reinterpret_cast<const float4*>(rp + 12);
                        const float X16 = rp[16];
                        const float* wk = &wbuf2[(icl*27 + kd*9 + kh*3)*32 + ocp];
                        const float w0a = wk[0],  w0b = wk[16];
                        const float w1a = wk[32], w1b = wk[48];
                        const float w2a = wk[64], w2b = wk[80];
                        EF2_KW(w0a, w0b, A0.x,A0.z,A1.x,A1.z,A2.x,A2.z,A3.x,A3.z)
                        EF2_KW(w1a, w1b, A0.y,A0.w,A1.y,A1.w,A2.y,A2.w,A3.y,A3.w)
                        EF2_KW(w2a, w2b, A0.z,A1.x,A1.z,A2.x,A2.z,A3.x,A3.z,X16)
                    }
                }
            }
            __syncthreads();
        }
        // y half = relu(acc + b2) -> global scratch (32B-contiguous per oc)
        {
            int spg = (4*q + od_l)*64 + oh2*8;
            #pragma unroll
            for (int o = 0; o < 2; o++) {
                int oc = ocp + 16*o;
                float bb = sb2[oc];
                float4 v0, v1;
                v0.x = fmaxf(acc[o][0] + bb, 0.f);
                v0.y = fmaxf(acc[o][1] + bb, 0.f);
                v0.z = fmaxf(acc[o][2] + bb, 0.f);
                v0.w = fmaxf(acc[o][3] + bb, 0.f);
                v1.x = fmaxf(acc[o][4] + bb, 0.f);
                v1.y = fmaxf(acc[o][5] + bb, 0.f);
                v1.z = fmaxf(acc[o][6] + bb, 0.f);
                v1.w = fmaxf(acc[o][7] + bb, 0.f);
                *reinterpret_cast<float4*>(ye + oc*512 + spg)     = v0;
                *reinterpret_cast<float4*>(ye + oc*512 + spg + 4) = v1;
                #pragma unroll
                for (int w = 0; w < 8; w++) acc[o][w] = 0.f;
            }
        }
    }
    __syncthreads();

    // conv3: thread = (sp3 = tid>>3, ocg3 = tid&7), 8 oc each
    const int sp3 = tid >> 3;
    const int ocg3 = tid & 7;
    const int od3 = sp3 >> 4, oh3 = (sp3 >> 2) & 3, ow3 = sp3 & 3;
    float acc3[8] = {0,0,0,0,0,0,0,0};

    for (int icg = 0; icg < 8; icg++) {
        // stage y chunk (4 ic x 512, stride 520) + W3 chunk
        {
            for (int i = tid; i < 512; i += 512) {   // 512 float4 = 2048 floats
                int icl = i >> 7, w4 = (i & 127) * 4;
                float4 v = *reinterpret_cast<const float4*>(ye + (icg*4 + icl)*512 + w4);
                *reinterpret_cast<float4*>(&ystage[icl*520 + w4]) = v;
            }
            const float4* src = reinterpret_cast<const float4*>(g_W3t + icg*6912);
            float4* dst = reinterpret_cast<float4*>(wbuf3);
            for (int i = tid; i < 1728; i += 512) dst[i] = src[i];
        }
        __syncthreads();
        #pragma unroll
        for (int icl = 0; icl < 4; icl++) {
            const float* yb = &ystage[icl*520];
            float yv[27];
            #pragma unroll
            for (int kd = 0; kd < 3; kd++) {
                int d = 2*od3 + kd;
                #pragma unroll
                for (int kh = 0; kh < 3; kh++) {
                    int h = 2*oh3 + kh;
                    #pragma unroll
                    for (int kw = 0; kw < 3; kw++) {
                        int w = 2*ow3 + kw;
                        yv[kd*9 + kh*3 + kw] =
                            (d < 8 && h < 8 && w < 8) ? yb[d*64 + h*8 + w] : 0.f;
                    }
                }
            }
            #pragma unroll
            for (int k = 0; k < 27; k++) {
                const float* wrow = &wbuf3[(icl*27 + k)*64 + ocg3*8];
                float4 wa = *reinterpret_cast<const float4*>(wrow);
                float4 wb = *reinterpret_cast<const float4*>(wrow + 4);
                float yk = yv[k];
                acc3[0] = fmaf(yk, wa.x, acc3[0]);
                acc3[1] = fmaf(yk, wa.y, acc3[1]);
                acc3[2] = fmaf(yk, wa.z, acc3[2]);
                acc3[3] = fmaf(yk, wa.w, acc3[3]);
                acc3[4] = fmaf(yk, wb.x, acc3[4]);
                acc3[5] = fmaf(yk, wb.y, acc3[5]);
                acc3[6] = fmaf(yk, wb.z, acc3[6]);
                acc3[7] = fmaf(yk, wb.w, acc3[7]);
            }
        }
        __syncthreads();
    }

    // z = relu(acc3 + b3) -> zbuf (stride 65)
    #pragma unroll
    for (int o = 0; o < 8; o++) {
        int oc = o*8 + ocg3;
        zbuf[oc*65 + sp3] = fmaxf(acc3[o] + b3[oc], 0.f);
    }
    __syncthreads();

    if (tid < 64) {
        float ssum = 0.f;
        #pragma unroll 8
        for (int qq = 0; qq < 64; qq++) ssum += zbuf[tid*65 + qq];
        pooled[tid] = ssum * (1.f/64.f);
    }
    __syncthreads();
    if (tid < 64) {
        float a = bfc[tid];
        #pragma unroll 8
        for (int ic = 0; ic < 64; ic++)
            a = fmaf(pooled[ic], Wfc[ic*64 + tid], a);
        out[e*64 + tid] = a;
    }
}

// ---------------------------------------------------------------- launch
extern "C" void kernel_launch(void* const* d_in, const int* in_sizes, int n_in,
                              void* d_out, int out_size)
{
    const float* data   = (const float*)d_in[0];
    const int*   clusts = (const int*)d_in[1];
    const int*   cmask  = (const int*)d_in[2];
    const int*   eidx   = (const int*)d_in[3];
    const float* W1  = (const float*)d_in[4];
    const float* b1  = (const float*)d_in[5];
    const float* W2  = (const float*)d_in[6];
    const float* b2  = (const float*)d_in[7];
    const float* W3  = (const float*)d_in[8];
    const float* b3  = (const float*)d_in[9];
    const float* Wfc = (const float*)d_in[10];
    const float* bfc = (const float*)d_in[11];
    float* out = (float*)d_out;

    const int C = in_sizes[1] / NP;       // 256
    const int E = in_sizes[3] / 2;        // 1024

    cudaFuncSetAttribute(voxconv1_kernel, cudaFuncAttributeMaxDynamicSharedMemorySize, K1_FLOATS*4);
    cudaFuncSetAttribute(edge_kernel,     cudaFuncAttributeMaxDynamicSharedMemorySize, E_SMEM);

    voxconv1_kernel<<<C, 512, K1_FLOATS*4>>>(data, clusts, cmask, W1, W2, W3);
    edge_kernel    <<<E, 512, E_SMEM>>>(eidx, E, C - 1, b1, b2, b3, Wfc, bfc, out);
}